// round 4
// baseline (speedup 1.0000x reference)
#include <cuda_runtime.h>

#define N_NODES 50000
#define N_EDGES 800000
#define TOTAL_EDGES (N_EDGES + N_NODES)   // + self loops
#define HC  512                           // HEADS * OUT_CH
#define HC4 128                           // float4s per node row

// ---- scratch (device globals: allocation-free, float4-typed => 16B aligned) ----
__device__ float4 g_xl[N_NODES * HC4];    // 102.4 MB, x_l rows
__device__ float4 g_xr[N_NODES * HC4];    // 102.4 MB, x_r rows
__device__ int    g_count[N_NODES];
__device__ int    g_off[N_NODES + 1];
__device__ int    g_cur[N_NODES];
__device__ int    g_csr[TOTAL_EDGES];     // src per dst-grouped slot
__device__ int    g_src[N_EDGES];
__device__ int    g_dst[N_EDGES];
__device__ int    g_not64;                // 1 if edge_index is int32, 0 if int64

// ---------------------------------------------------------------------------
__global__ void k_zero() {
    int i = blockIdx.x * blockDim.x + threadIdx.x;
    if (i < N_NODES) g_count[i] = 0;
    if (i == 0) g_not64 = 0;
}

// Probe dtype of edge_index. Reads only the first N_EDGES int64 words (6.4 MB),
// in-bounds under either dtype. True int64 values are all in [0, N_NODES);
// misread int32 pairs have nonzero high words almost surely -> flag.
__global__ void k_detect(const long long* __restrict__ ei64) {
    int e = blockIdx.x * blockDim.x + threadIdx.x;
    if (e < N_EDGES) {
        long long v = ei64[e];
        if (v < 0 || v >= N_NODES) g_not64 = 1;   // benign race, all write 1
    }
}

// Convert to int32 src/dst AND build the degree histogram in one pass.
__global__ void k_convert_count(const void* __restrict__ ei_raw) {
    int e = blockIdx.x * blockDim.x + threadIdx.x;
    if (e >= N_EDGES) return;
    int s, d;
    if (g_not64) {
        const int* ei32 = (const int*)ei_raw;
        s = ei32[e];
        d = ei32[N_EDGES + e];
    } else {
        const long long* ei64 = (const long long*)ei_raw;
        s = (int)ei64[e];
        d = (int)ei64[N_EDGES + e];
    }
    g_src[e] = s;
    g_dst[e] = d;
    atomicAdd(&g_count[d], 1);
}

// Single-block exclusive scan over per-node degrees (+1 for self loop).
__global__ void k_scan() {
    __shared__ int sm[1024];
    int t = threadIdx.x;
    const int IT = (N_NODES + 1023) / 1024;   // 49
    int beg = t * IT;
    int end = beg + IT; if (end > N_NODES) end = N_NODES;
    int s = 0;
    for (int i = beg; i < end; i++) s += g_count[i] + 1;
    sm[t] = s;
    __syncthreads();
    for (int off = 1; off < 1024; off <<= 1) {
        int v = 0;
        if (t >= off) v = sm[t - off];
        __syncthreads();
        sm[t] += v;
        __syncthreads();
    }
    int run = sm[t] - s;                      // exclusive prefix for this chunk
    for (int i = beg; i < end; i++) {
        g_off[i] = run;
        g_cur[i] = run;
        run += g_count[i] + 1;
    }
    if (t == 1023) g_off[N_NODES] = sm[1023];
}

__global__ void k_scatter() {
    int e = blockIdx.x * blockDim.x + threadIdx.x;
    if (e < N_EDGES) {
        int p = atomicAdd(&g_cur[g_dst[e]], 1);
        g_csr[p] = g_src[e];
    } else if (e < TOTAL_EDGES) {
        int n = e - N_EDGES;                  // self loop n -> n
        int p = atomicAdd(&g_cur[n], 1);
        g_csr[p] = n;
    }
}

// x_l = X @ W_l, x_r = X @ W_r   (K=16, write-bound)
__global__ void k_transform(const float* __restrict__ X,
                            const float* __restrict__ Wl,
                            const float* __restrict__ Wr) {
    int idx = blockIdx.x * blockDim.x + threadIdx.x;   // over N_NODES*HC4 float4s
    if (idx >= N_NODES * HC4) return;
    int n = idx >> 7;
    int j = idx & 127;
    const float4* wl4 = (const float4*)Wl;
    const float4* wr4 = (const float4*)Wr;
    float4 al = make_float4(0.f, 0.f, 0.f, 0.f);
    float4 ar = make_float4(0.f, 0.f, 0.f, 0.f);
#pragma unroll
    for (int k = 0; k < 16; k++) {
        float  xv = X[n * 16 + k];                     // warp-uniform broadcast
        float4 wl = wl4[k * HC4 + j];
        float4 wr = wr4[k * HC4 + j];
        al.x = fmaf(xv, wl.x, al.x); al.y = fmaf(xv, wl.y, al.y);
        al.z = fmaf(xv, wl.z, al.z); al.w = fmaf(xv, wl.w, al.w);
        ar.x = fmaf(xv, wr.x, ar.x); ar.y = fmaf(xv, wr.y, ar.y);
        ar.z = fmaf(xv, wr.z, ar.z); ar.w = fmaf(xv, wr.w, ar.w);
    }
    g_xl[idx] = al;
    g_xr[idx] = ar;
}

// Fused GATv2 score + softmax + aggregation. One block (128 thr) per dst node,
// thread t owns channels [4t, 4t+4), warp w == head w. Edge loop unrolled 4x
// so each warp keeps 4 independent float4 gathers in flight (MLP=4).
// Softmax shift dropped (scores bounded; exp can't overflow in fp32):
// exp(s)/sum exp(s) is identical to the max-shifted reference.

__device__ __forceinline__ float edge_score(float4 cx, float4 xr, float4 a) {
    float vx = cx.x + xr.x; vx = vx > 0.f ? vx : 0.2f * vx;
    float vy = cx.y + xr.y; vy = vy > 0.f ? vy : 0.2f * vy;
    float vz = cx.z + xr.z; vz = vz > 0.f ? vz : 0.2f * vz;
    float vw = cx.w + xr.w; vw = vw > 0.f ? vw : 0.2f * vw;
    float s = a.x * vx;
    s = fmaf(a.y, vy, s);
    s = fmaf(a.z, vz, s);
    s = fmaf(a.w, vw, s);
    return s;
}

__global__ void __launch_bounds__(128) k_aggregate(const float* __restrict__ att,
                                                   const float* __restrict__ bias,
                                                   float* __restrict__ out) {
    int node = blockIdx.x;
    int t    = threadIdx.x;

    float4 xr = g_xr[node * HC4 + t];
    float4 a  = ((const float4*)att)[t];    // att flat [h*128+c] == channels [4t..4t+3]

    float4 acc = make_float4(0.f, 0.f, 0.f, 0.f);
    float  d   = 0.f;

    int p   = g_off[node];
    int end = g_off[node + 1];

    // ---- main loop: 4 edges per iteration, 4 gathers in flight ----
    for (; p + 4 <= end; p += 4) {
        int s0 = g_csr[p + 0];
        int s1 = g_csr[p + 1];
        int s2 = g_csr[p + 2];
        int s3 = g_csr[p + 3];
        float4 c0 = g_xl[s0 * HC4 + t];
        float4 c1 = g_xl[s1 * HC4 + t];
        float4 c2 = g_xl[s2 * HC4 + t];
        float4 c3 = g_xl[s3 * HC4 + t];

        float sc0 = edge_score(c0, xr, a);
        float sc1 = edge_score(c1, xr, a);
        float sc2 = edge_score(c2, xr, a);
        float sc3 = edge_score(c3, xr, a);
#pragma unroll
        for (int m = 16; m >= 1; m >>= 1) {
            sc0 += __shfl_xor_sync(0xffffffffu, sc0, m);
            sc1 += __shfl_xor_sync(0xffffffffu, sc1, m);
            sc2 += __shfl_xor_sync(0xffffffffu, sc2, m);
            sc3 += __shfl_xor_sync(0xffffffffu, sc3, m);
        }
        float e0 = __expf(sc0);
        float e1 = __expf(sc1);
        float e2 = __expf(sc2);
        float e3 = __expf(sc3);
        d += (e0 + e1) + (e2 + e3);
        acc.x = fmaf(e0, c0.x, acc.x); acc.y = fmaf(e0, c0.y, acc.y);
        acc.z = fmaf(e0, c0.z, acc.z); acc.w = fmaf(e0, c0.w, acc.w);
        acc.x = fmaf(e1, c1.x, acc.x); acc.y = fmaf(e1, c1.y, acc.y);
        acc.z = fmaf(e1, c1.z, acc.z); acc.w = fmaf(e1, c1.w, acc.w);
        acc.x = fmaf(e2, c2.x, acc.x); acc.y = fmaf(e2, c2.y, acc.y);
        acc.z = fmaf(e2, c2.z, acc.z); acc.w = fmaf(e2, c2.w, acc.w);
        acc.x = fmaf(e3, c3.x, acc.x); acc.y = fmaf(e3, c3.y, acc.y);
        acc.z = fmaf(e3, c3.z, acc.z); acc.w = fmaf(e3, c3.w, acc.w);
    }

    // ---- remainder (0..3 edges; self loop guarantees end > off) ----
    for (; p < end; p++) {
        int    s  = g_csr[p];
        float4 cx = g_xl[s * HC4 + t];
        float  sc = edge_score(cx, xr, a);
#pragma unroll
        for (int m = 16; m >= 1; m >>= 1)
            sc += __shfl_xor_sync(0xffffffffu, sc, m);
        float e = __expf(sc);
        d += e;
        acc.x = fmaf(e, cx.x, acc.x);
        acc.y = fmaf(e, cx.y, acc.y);
        acc.z = fmaf(e, cx.z, acc.z);
        acc.w = fmaf(e, cx.w, acc.w);
    }

    float inv = 1.0f / d;
    float4 b = ((const float4*)bias)[t];
    float4 o;
    o.x = fmaf(acc.x, inv, b.x);
    o.y = fmaf(acc.y, inv, b.y);
    o.z = fmaf(acc.z, inv, b.z);
    o.w = fmaf(acc.w, inv, b.w);
    ((float4*)out)[node * HC4 + t] = o;
}

// ---------------------------------------------------------------------------
extern "C" void kernel_launch(void* const* d_in, const int* in_sizes, int n_in,
                              void* d_out, int out_size) {
    const float* X    = (const float*)d_in[0];       // [50000,16]
    const void*  ei   = d_in[1];                     // [2,800000] int32 or int64
    const float* Wl   = (const float*)d_in[2];       // [16,512]
    const float* Wr   = (const float*)d_in[3];       // [16,512]
    const float* att  = (const float*)d_in[4];       // [4,128]
    const float* bias = (const float*)d_in[5];       // [512]
    float*       out  = (float*)d_out;               // [50000,512]

    k_zero<<<(N_NODES + 255) / 256, 256>>>();
    k_detect<<<(N_EDGES + 255) / 256, 256>>>((const long long*)ei);
    k_convert_count<<<(N_EDGES + 255) / 256, 256>>>(ei);
    k_transform<<<(N_NODES * HC4 + 255) / 256, 256>>>(X, Wl, Wr);
    k_scan<<<1, 1024>>>();
    k_scatter<<<(TOTAL_EDGES + 255) / 256, 256>>>();
    k_aggregate<<<N_NODES, 128>>>(att, bias, out);
}

// round 5
// speedup vs baseline: 1.1758x; 1.1758x over previous
#include <cuda_runtime.h>
#include <cstdint>

#define N_NODES 50000
#define N_EDGES 800000
#define TOTAL_EDGES (N_EDGES + N_NODES)   // + self loops
#define HC  512                           // HEADS * OUT_CH
#define HC4 128                           // float4s per node row
#define HC2 256                           // float2s per node row

// ---- scratch (device globals: allocation-free, float4-typed => 16B aligned) ----
__device__ float4 g_xl[N_NODES * HC4];    // 102.4 MB, x_l rows
__device__ float4 g_xr[N_NODES * HC4];    // 102.4 MB, x_r rows
__device__ int    g_count[N_NODES];
__device__ int    g_off[N_NODES + 1];
__device__ int    g_cur[N_NODES];
__device__ int    g_csr[TOTAL_EDGES];     // src per dst-grouped slot
__device__ int    g_src[N_EDGES];
__device__ int    g_dst[N_EDGES];
__device__ int    g_not64;                // 1 if edge_index is int32, 0 if int64

// ---------------------------------------------------------------------------
__global__ void k_zero() {
    int i = blockIdx.x * blockDim.x + threadIdx.x;
    if (i < N_NODES) g_count[i] = 0;
    if (i == 0) g_not64 = 0;
}

// Probe dtype of edge_index. Reads only the first N_EDGES int64 words (6.4 MB),
// in-bounds under either dtype. True int64 values are all in [0, N_NODES);
// misread int32 pairs have nonzero high words almost surely -> flag.
__global__ void k_detect(const long long* __restrict__ ei64) {
    int e = blockIdx.x * blockDim.x + threadIdx.x;
    if (e < N_EDGES) {
        long long v = ei64[e];
        if (v < 0 || v >= N_NODES) g_not64 = 1;   // benign race, all write 1
    }
}

// Convert to int32 src/dst AND build the degree histogram in one pass.
__global__ void k_convert_count(const void* __restrict__ ei_raw) {
    int e = blockIdx.x * blockDim.x + threadIdx.x;
    if (e >= N_EDGES) return;
    int s, d;
    if (g_not64) {
        const int* ei32 = (const int*)ei_raw;
        s = ei32[e];
        d = ei32[N_EDGES + e];
    } else {
        const long long* ei64 = (const long long*)ei_raw;
        s = (int)ei64[e];
        d = (int)ei64[N_EDGES + e];
    }
    g_src[e] = s;
    g_dst[e] = d;
    atomicAdd(&g_count[d], 1);
}

// ---------------------------------------------------------------------------
// x_l = X @ W_l, x_r = X @ W_r with register-resident W.
// 256 threads/block; thread c owns channels {2c, 2c+1} as one packed f32x2.
// W slice per thread: 16 K-values x 2 channels x 2 mats = 32 x u64 registers,
// loaded ONCE per block. Block processes NODES_PER_BLOCK nodes; X rows staged
// via smem. Inner product uses packed fma.rn.f32x2 (2 FMAs/instr).
#define NODES_PER_BLOCK 64
#define XBATCH 32

__global__ void __launch_bounds__(256) k_transform(const float* __restrict__ X,
                                                   const float* __restrict__ Wl,
                                                   const float* __restrict__ Wr) {
    int c   = threadIdx.x;                 // channel pair 0..255
    int nb0 = blockIdx.x * NODES_PER_BLOCK;

    // Load W columns into registers (once per block).
    unsigned long long wl[16], wr[16];
    const unsigned long long* wl2 = (const unsigned long long*)Wl;  // [16][256] f32x2
    const unsigned long long* wr2 = (const unsigned long long*)Wr;
#pragma unroll
    for (int k = 0; k < 16; k++) {
        wl[k] = wl2[k * HC2 + c];
        wr[k] = wr2[k * HC2 + c];
    }

    __shared__ float xs[XBATCH][16];
    unsigned long long* xl2 = (unsigned long long*)g_xl;
    unsigned long long* xr2 = (unsigned long long*)g_xr;

    for (int base = nb0; base < nb0 + NODES_PER_BLOCK; base += XBATCH) {
        // Stage XBATCH node rows of X (coalesced: 512 floats by 256 threads).
        __syncthreads();
        {
            int i0 = c;                    // 2 elements per thread
            int n0 = base + (i0 >> 4);
            if (n0 < N_NODES) xs[i0 >> 4][i0 & 15] = X[n0 * 16 + (i0 & 15)];
            int i1 = c + 256;
            int n1 = base + (i1 >> 4);
            if (n1 < N_NODES) xs[i1 >> 4][i1 & 15] = X[n1 * 16 + (i1 & 15)];
        }
        __syncthreads();

        for (int i = 0; i < XBATCH; i++) {
            int node = base + i;
            if (node >= N_NODES) break;
            unsigned long long al = 0, ar = 0;
            // zero-init packed accumulators via first mul
            {
                float xv = xs[i][0];
                unsigned long long xp;
                asm("mov.b64 %0, {%1, %1};" : "=l"(xp) : "f"(xv));
                asm("mul.rn.f32x2 %0, %1, %2;" : "=l"(al) : "l"(xp), "l"(wl[0]));
                asm("mul.rn.f32x2 %0, %1, %2;" : "=l"(ar) : "l"(xp), "l"(wr[0]));
            }
#pragma unroll
            for (int k = 1; k < 16; k++) {
                float xv = xs[i][k];
                unsigned long long xp;
                asm("mov.b64 %0, {%1, %1};" : "=l"(xp) : "f"(xv));
                asm("fma.rn.f32x2 %0, %1, %2, %3;" : "=l"(al) : "l"(xp), "l"(wl[k]), "l"(al));
                asm("fma.rn.f32x2 %0, %1, %2, %3;" : "=l"(ar) : "l"(xp), "l"(wr[k]), "l"(ar));
            }
            xl2[(size_t)node * HC2 + c] = al;
            xr2[(size_t)node * HC2 + c] = ar;
        }
    }
}

// Single-block exclusive scan over per-node degrees (+1 for self loop).
__global__ void k_scan() {
    __shared__ int sm[1024];
    int t = threadIdx.x;
    const int IT = (N_NODES + 1023) / 1024;   // 49
    int beg = t * IT;
    int end = beg + IT; if (end > N_NODES) end = N_NODES;
    int s = 0;
    for (int i = beg; i < end; i++) s += g_count[i] + 1;
    sm[t] = s;
    __syncthreads();
    for (int off = 1; off < 1024; off <<= 1) {
        int v = 0;
        if (t >= off) v = sm[t - off];
        __syncthreads();
        sm[t] += v;
        __syncthreads();
    }
    int run = sm[t] - s;                      // exclusive prefix for this chunk
    for (int i = beg; i < end; i++) {
        g_off[i] = run;
        g_cur[i] = run;
        run += g_count[i] + 1;
    }
    if (t == 1023) g_off[N_NODES] = sm[1023];
}

__global__ void k_scatter() {
    int e = blockIdx.x * blockDim.x + threadIdx.x;
    if (e < N_EDGES) {
        int p = atomicAdd(&g_cur[g_dst[e]], 1);
        g_csr[p] = g_src[e];
    } else if (e < TOTAL_EDGES) {
        int n = e - N_EDGES;                  // self loop n -> n
        int p = atomicAdd(&g_cur[n], 1);
        g_csr[p] = n;
    }
}

// ---------------------------------------------------------------------------
// Fused GATv2 score + softmax + aggregation. One block (128 thr) per dst node,
// thread t owns channels [4t, 4t+4), warp w == head w. Edge loop unrolled 4x.
// Softmax shift dropped (scores bounded; exp can't overflow in fp32):
// exp(s)/sum exp(s) is identical to the max-shifted reference.
__device__ __forceinline__ float edge_score(float4 cx, float4 xr, float4 a) {
    float vx = cx.x + xr.x; vx = vx > 0.f ? vx : 0.2f * vx;
    float vy = cx.y + xr.y; vy = vy > 0.f ? vy : 0.2f * vy;
    float vz = cx.z + xr.z; vz = vz > 0.f ? vz : 0.2f * vz;
    float vw = cx.w + xr.w; vw = vw > 0.f ? vw : 0.2f * vw;
    float s = a.x * vx;
    s = fmaf(a.y, vy, s);
    s = fmaf(a.z, vz, s);
    s = fmaf(a.w, vw, s);
    return s;
}

__global__ void __launch_bounds__(128) k_aggregate(const float* __restrict__ att,
                                                   const float* __restrict__ bias,
                                                   float* __restrict__ out) {
    int node = blockIdx.x;
    int t    = threadIdx.x;

    float4 xr = g_xr[node * HC4 + t];
    float4 a  = ((const float4*)att)[t];    // att flat [h*128+c] == channels [4t..4t+3]

    float4 acc = make_float4(0.f, 0.f, 0.f, 0.f);
    float  d   = 0.f;

    int p   = g_off[node];
    int end = g_off[node + 1];

    // ---- main loop: 4 edges per iteration, 4 gathers in flight ----
    for (; p + 4 <= end; p += 4) {
        int s0 = g_csr[p + 0];
        int s1 = g_csr[p + 1];
        int s2 = g_csr[p + 2];
        int s3 = g_csr[p + 3];
        float4 c0 = g_xl[s0 * HC4 + t];
        float4 c1 = g_xl[s1 * HC4 + t];
        float4 c2 = g_xl[s2 * HC4 + t];
        float4 c3 = g_xl[s3 * HC4 + t];

        float sc0 = edge_score(c0, xr, a);
        float sc1 = edge_score(c1, xr, a);
        float sc2 = edge_score(c2, xr, a);
        float sc3 = edge_score(c3, xr, a);
#pragma unroll
        for (int m = 16; m >= 1; m >>= 1) {
            sc0 += __shfl_xor_sync(0xffffffffu, sc0, m);
            sc1 += __shfl_xor_sync(0xffffffffu, sc1, m);
            sc2 += __shfl_xor_sync(0xffffffffu, sc2, m);
            sc3 += __shfl_xor_sync(0xffffffffu, sc3, m);
        }
        float e0 = __expf(sc0);
        float e1 = __expf(sc1);
        float e2 = __expf(sc2);
        float e3 = __expf(sc3);
        d += (e0 + e1) + (e2 + e3);
        acc.x = fmaf(e0, c0.x, acc.x); acc.y = fmaf(e0, c0.y, acc.y);
        acc.z = fmaf(e0, c0.z, acc.z); acc.w = fmaf(e0, c0.w, acc.w);
        acc.x = fmaf(e1, c1.x, acc.x); acc.y = fmaf(e1, c1.y, acc.y);
        acc.z = fmaf(e1, c1.z, acc.z); acc.w = fmaf(e1, c1.w, acc.w);
        acc.x = fmaf(e2, c2.x, acc.x); acc.y = fmaf(e2, c2.y, acc.y);
        acc.z = fmaf(e2, c2.z, acc.z); acc.w = fmaf(e2, c2.w, acc.w);
        acc.x = fmaf(e3, c3.x, acc.x); acc.y = fmaf(e3, c3.y, acc.y);
        acc.z = fmaf(e3, c3.z, acc.z); acc.w = fmaf(e3, c3.w, acc.w);
    }

    // ---- remainder (0..3 edges; self loop guarantees end > off) ----
    for (; p < end; p++) {
        int    s  = g_csr[p];
        float4 cx = g_xl[s * HC4 + t];
        float  sc = edge_score(cx, xr, a);
#pragma unroll
        for (int m = 16; m >= 1; m >>= 1)
            sc += __shfl_xor_sync(0xffffffffu, sc, m);
        float e = __expf(sc);
        d += e;
        acc.x = fmaf(e, cx.x, acc.x);
        acc.y = fmaf(e, cx.y, acc.y);
        acc.z = fmaf(e, cx.z, acc.z);
        acc.w = fmaf(e, cx.w, acc.w);
    }

    float inv = 1.0f / d;
    float4 b = ((const float4*)bias)[t];
    float4 o;
    o.x = fmaf(acc.x, inv, b.x);
    o.y = fmaf(acc.y, inv, b.y);
    o.z = fmaf(acc.z, inv, b.z);
    o.w = fmaf(acc.w, inv, b.w);
    ((float4*)out)[node * HC4 + t] = o;
}

// ---------------------------------------------------------------------------
extern "C" void kernel_launch(void* const* d_in, const int* in_sizes, int n_in,
                              void* d_out, int out_size) {
    const float* X    = (const float*)d_in[0];       // [50000,16]
    const void*  ei   = d_in[1];                     // [2,800000] int32 or int64
    const float* Wl   = (const float*)d_in[2];       // [16,512]
    const float* Wr   = (const float*)d_in[3];       // [16,512]
    const float* att  = (const float*)d_in[4];       // [4,128]
    const float* bias = (const float*)d_in[5];       // [512]
    float*       out  = (float*)d_out;               // [50000,512]

    k_zero<<<(N_NODES + 255) / 256, 256>>>();
    k_detect<<<(N_EDGES + 255) / 256, 256>>>((const long long*)ei);
    k_convert_count<<<(N_EDGES + 255) / 256, 256>>>(ei);
    k_transform<<<(N_NODES + NODES_PER_BLOCK - 1) / NODES_PER_BLOCK, 256>>>(X, Wl, Wr);
    k_scan<<<1, 1024>>>();
    k_scatter<<<(TOTAL_EDGES + 255) / 256, 256>>>();
    k_aggregate<<<N_NODES, 128>>>(att, bias, out);
}

// round 6
// speedup vs baseline: 1.2984x; 1.1043x over previous
#include <cuda_runtime.h>
#include <cuda_fp16.h>
#include <cstdint>

#define N_NODES 50000
#define N_EDGES 800000
#define TOTAL_EDGES (N_EDGES + N_NODES)   // + self loops
#define HC  512                           // HEADS * OUT_CH
#define HC4 128                           // float4s / uint2s per node row
#define HC2 256                           // float2s / half2s per node row

// ---- scratch (device globals: allocation-free) ----
__device__ uint2  g_xlh[N_NODES * HC4];   // 51.2 MB, x_l rows in fp16 (gather stream)
__device__ float4 g_xr[N_NODES * HC4];    // 102.4 MB, x_r rows fp32
__device__ int    g_count[N_NODES];
__device__ int    g_off[N_NODES + 1];
__device__ int    g_cur[N_NODES];
__device__ int    g_csr[TOTAL_EDGES];     // src per dst-grouped slot
__device__ int    g_src[N_EDGES];
__device__ int    g_dst[N_EDGES];
__device__ int    g_not64;                // 1 if edge_index is int32, 0 if int64

// ---------------------------------------------------------------------------
__global__ void k_zero() {
    int i = blockIdx.x * blockDim.x + threadIdx.x;
    if (i < N_NODES) g_count[i] = 0;
    if (i == 0) g_not64 = 0;
}

// Probe dtype of edge_index. Reads only the first N_EDGES int64 words (6.4 MB),
// in-bounds under either dtype. True int64 values are all in [0, N_NODES);
// misread int32 pairs have nonzero high words almost surely -> flag.
__global__ void k_detect(const long long* __restrict__ ei64) {
    int e = blockIdx.x * blockDim.x + threadIdx.x;
    if (e < N_EDGES) {
        long long v = ei64[e];
        if (v < 0 || v >= N_NODES) g_not64 = 1;   // benign race, all write 1
    }
}

// Convert to int32 src/dst AND build the degree histogram in one pass.
__global__ void k_convert_count(const void* __restrict__ ei_raw) {
    int e = blockIdx.x * blockDim.x + threadIdx.x;
    if (e >= N_EDGES) return;
    int s, d;
    if (g_not64) {
        const int* ei32 = (const int*)ei_raw;
        s = ei32[e];
        d = ei32[N_EDGES + e];
    } else {
        const long long* ei64 = (const long long*)ei_raw;
        s = (int)ei64[e];
        d = (int)ei64[N_EDGES + e];
    }
    g_src[e] = s;
    g_dst[e] = d;
    atomicAdd(&g_count[d], 1);
}

// ---------------------------------------------------------------------------
// x_l = X @ W_l (stored fp16), x_r = X @ W_r (stored fp32).
// Register-resident W: 256 threads/block, thread c owns channels {2c, 2c+1}.
// W slice = 32 packed u64 regs, loaded once per block. X staged via smem.
// Packed fma.rn.f32x2 halves FMA issue count.
#define NODES_PER_BLOCK 64
#define XBATCH 32

__global__ void __launch_bounds__(256) k_transform(const float* __restrict__ X,
                                                   const float* __restrict__ Wl,
                                                   const float* __restrict__ Wr) {
    int c   = threadIdx.x;                 // channel pair 0..255
    int nb0 = blockIdx.x * NODES_PER_BLOCK;

    unsigned long long wl[16], wr[16];
    const unsigned long long* wl2 = (const unsigned long long*)Wl;  // [16][256] f32x2
    const unsigned long long* wr2 = (const unsigned long long*)Wr;
#pragma unroll
    for (int k = 0; k < 16; k++) {
        wl[k] = wl2[k * HC2 + c];
        wr[k] = wr2[k * HC2 + c];
    }

    __shared__ float xs[XBATCH][16];
    unsigned long long* xr2 = (unsigned long long*)g_xr;
    __half2*            xlh = (__half2*)g_xlh;

    for (int base = nb0; base < nb0 + NODES_PER_BLOCK; base += XBATCH) {
        __syncthreads();
        {
            int i0 = c;                    // 2 X elements per thread
            int n0 = base + (i0 >> 4);
            if (n0 < N_NODES) xs[i0 >> 4][i0 & 15] = X[n0 * 16 + (i0 & 15)];
            int i1 = c + 256;
            int n1 = base + (i1 >> 4);
            if (n1 < N_NODES) xs[i1 >> 4][i1 & 15] = X[n1 * 16 + (i1 & 15)];
        }
        __syncthreads();

        for (int i = 0; i < XBATCH; i++) {
            int node = base + i;
            if (node >= N_NODES) break;
            unsigned long long al, ar;
            {
                float xv = xs[i][0];
                unsigned long long xp;
                asm("mov.b64 %0, {%1, %1};" : "=l"(xp) : "f"(xv));
                asm("mul.rn.f32x2 %0, %1, %2;" : "=l"(al) : "l"(xp), "l"(wl[0]));
                asm("mul.rn.f32x2 %0, %1, %2;" : "=l"(ar) : "l"(xp), "l"(wr[0]));
            }
#pragma unroll
            for (int k = 1; k < 16; k++) {
                float xv = xs[i][k];
                unsigned long long xp;
                asm("mov.b64 %0, {%1, %1};" : "=l"(xp) : "f"(xv));
                asm("fma.rn.f32x2 %0, %1, %2, %3;" : "=l"(al) : "l"(xp), "l"(wl[k]), "l"(al));
                asm("fma.rn.f32x2 %0, %1, %2, %3;" : "=l"(ar) : "l"(xp), "l"(wr[k]), "l"(ar));
            }
            // x_r: fp32 packed store
            xr2[(size_t)node * HC2 + c] = ar;
            // x_l: fp16 mirror
            float lo, hi;
            asm("mov.b64 {%0, %1}, %2;" : "=f"(lo), "=f"(hi) : "l"(al));
            xlh[(size_t)node * HC2 + c] = __floats2half2_rn(lo, hi);
        }
    }
}

// Single-block exclusive scan over per-node degrees (+1 for self loop).
__global__ void k_scan() {
    __shared__ int sm[1024];
    int t = threadIdx.x;
    const int IT = (N_NODES + 1023) / 1024;   // 49
    int beg = t * IT;
    int end = beg + IT; if (end > N_NODES) end = N_NODES;
    int s = 0;
    for (int i = beg; i < end; i++) s += g_count[i] + 1;
    sm[t] = s;
    __syncthreads();
    for (int off = 1; off < 1024; off <<= 1) {
        int v = 0;
        if (t >= off) v = sm[t - off];
        __syncthreads();
        sm[t] += v;
        __syncthreads();
    }
    int run = sm[t] - s;                      // exclusive prefix for this chunk
    for (int i = beg; i < end; i++) {
        g_off[i] = run;
        g_cur[i] = run;
        run += g_count[i] + 1;
    }
    if (t == 1023) g_off[N_NODES] = sm[1023];
}

__global__ void k_scatter() {
    int e = blockIdx.x * blockDim.x + threadIdx.x;
    if (e < N_EDGES) {
        int p = atomicAdd(&g_cur[g_dst[e]], 1);
        g_csr[p] = g_src[e];
    } else if (e < TOTAL_EDGES) {
        int n = e - N_EDGES;                  // self loop n -> n
        int p = atomicAdd(&g_cur[n], 1);
        g_csr[p] = n;
    }
}

// ---------------------------------------------------------------------------
// Fused GATv2 score + softmax + aggregation. One block (128 thr) per dst node,
// thread t owns channels [4t, 4t+4), warp w == head w. x_l gathered as fp16
// (8 B per edge per thread), scored & accumulated in fp32. Unroll 4 keeps 4
// gathers in flight. Softmax shift dropped (scores bounded; exp can't
// overflow in fp32): exp(s)/sum exp(s) == max-shifted reference.
__device__ __forceinline__ float4 un16(uint2 r) {
    float2 f01 = __half22float2(*(__half2*)&r.x);
    float2 f23 = __half22float2(*(__half2*)&r.y);
    return make_float4(f01.x, f01.y, f23.x, f23.y);
}

__device__ __forceinline__ float edge_score(float4 cx, float4 xr, float4 a) {
    float vx = cx.x + xr.x; vx = vx > 0.f ? vx : 0.2f * vx;
    float vy = cx.y + xr.y; vy = vy > 0.f ? vy : 0.2f * vy;
    float vz = cx.z + xr.z; vz = vz > 0.f ? vz : 0.2f * vz;
    float vw = cx.w + xr.w; vw = vw > 0.f ? vw : 0.2f * vw;
    float s = a.x * vx;
    s = fmaf(a.y, vy, s);
    s = fmaf(a.z, vz, s);
    s = fmaf(a.w, vw, s);
    return s;
}

__global__ void __launch_bounds__(128) k_aggregate(const float* __restrict__ att,
                                                   const float* __restrict__ bias,
                                                   float* __restrict__ out) {
    int node = blockIdx.x;
    int t    = threadIdx.x;

    float4 xr = g_xr[node * HC4 + t];
    float4 a  = ((const float4*)att)[t];    // att flat [h*128+c] == channels [4t..4t+3]

    float4 acc = make_float4(0.f, 0.f, 0.f, 0.f);
    float  d   = 0.f;

    int p   = g_off[node];
    int end = g_off[node + 1];

    // ---- main loop: 4 edges per iteration, 4 gathers in flight ----
    for (; p + 4 <= end; p += 4) {
        int s0 = g_csr[p + 0];
        int s1 = g_csr[p + 1];
        int s2 = g_csr[p + 2];
        int s3 = g_csr[p + 3];
        uint2 r0 = g_xlh[s0 * HC4 + t];
        uint2 r1 = g_xlh[s1 * HC4 + t];
        uint2 r2 = g_xlh[s2 * HC4 + t];
        uint2 r3 = g_xlh[s3 * HC4 + t];
        float4 c0 = un16(r0);
        float4 c1 = un16(r1);
        float4 c2 = un16(r2);
        float4 c3 = un16(r3);

        float sc0 = edge_score(c0, xr, a);
        float sc1 = edge_score(c1, xr, a);
        float sc2 = edge_score(c2, xr, a);
        float sc3 = edge_score(c3, xr, a);
#pragma unroll
        for (int m = 16; m >= 1; m >>= 1) {
            sc0 += __shfl_xor_sync(0xffffffffu, sc0, m);
            sc1 += __shfl_xor_sync(0xffffffffu, sc1, m);
            sc2 += __shfl_xor_sync(0xffffffffu, sc2, m);
            sc3 += __shfl_xor_sync(0xffffffffu, sc3, m);
        }
        float e0 = __expf(sc0);
        float e1 = __expf(sc1);
        float e2 = __expf(sc2);
        float e3 = __expf(sc3);
        d += (e0 + e1) + (e2 + e3);
        acc.x = fmaf(e0, c0.x, acc.x); acc.y = fmaf(e0, c0.y, acc.y);
        acc.z = fmaf(e0, c0.z, acc.z); acc.w = fmaf(e0, c0.w, acc.w);
        acc.x = fmaf(e1, c1.x, acc.x); acc.y = fmaf(e1, c1.y, acc.y);
        acc.z = fmaf(e1, c1.z, acc.z); acc.w = fmaf(e1, c1.w, acc.w);
        acc.x = fmaf(e2, c2.x, acc.x); acc.y = fmaf(e2, c2.y, acc.y);
        acc.z = fmaf(e2, c2.z, acc.z); acc.w = fmaf(e2, c2.w, acc.w);
        acc.x = fmaf(e3, c3.x, acc.x); acc.y = fmaf(e3, c3.y, acc.y);
        acc.z = fmaf(e3, c3.z, acc.z); acc.w = fmaf(e3, c3.w, acc.w);
    }

    // ---- remainder (0..3 edges; self loop guarantees end > off) ----
    for (; p < end; p++) {
        int    s  = g_csr[p];
        float4 cx = un16(g_xlh[s * HC4 + t]);
        float  sc = edge_score(cx, xr, a);
#pragma unroll
        for (int m = 16; m >= 1; m >>= 1)
            sc += __shfl_xor_sync(0xffffffffu, sc, m);
        float e = __expf(sc);
        d += e;
        acc.x = fmaf(e, cx.x, acc.x);
        acc.y = fmaf(e, cx.y, acc.y);
        acc.z = fmaf(e, cx.z, acc.z);
        acc.w = fmaf(e, cx.w, acc.w);
    }

    float inv = 1.0f / d;
    float4 b = ((const float4*)bias)[t];
    float4 o;
    o.x = fmaf(acc.x, inv, b.x);
    o.y = fmaf(acc.y, inv, b.y);
    o.z = fmaf(acc.z, inv, b.z);
    o.w = fmaf(acc.w, inv, b.w);
    ((float4*)out)[node * HC4 + t] = o;
}

// ---------------------------------------------------------------------------
extern "C" void kernel_launch(void* const* d_in, const int* in_sizes, int n_in,
                              void* d_out, int out_size) {
    const float* X    = (const float*)d_in[0];       // [50000,16]
    const void*  ei   = d_in[1];                     // [2,800000] int32 or int64
    const float* Wl   = (const float*)d_in[2];       // [16,512]
    const float* Wr   = (const float*)d_in[3];       // [16,512]
    const float* att  = (const float*)d_in[4];       // [4,128]
    const float* bias = (const float*)d_in[5];       // [512]
    float*       out  = (float*)d_out;               // [50000,512]

    k_zero<<<(N_NODES + 255) / 256, 256>>>();
    k_detect<<<(N_EDGES + 255) / 256, 256>>>((const long long*)ei);
    k_convert_count<<<(N_EDGES + 255) / 256, 256>>>(ei);
    k_transform<<<(N_NODES + NODES_PER_BLOCK - 1) / NODES_PER_BLOCK, 256>>>(X, Wl, Wr);
    k_scan<<<1, 1024>>>();
    k_scatter<<<(TOTAL_EDGES + 255) / 256, 256>>>();
    k_aggregate<<<N_NODES, 128>>>(att, bias, out);
}